// round 1
// baseline (speedup 1.0000x reference)
#include <cuda_runtime.h>
#include <math.h>

#define B_  2048
#define N_  64
#define H_  512
#define L_  256
#define M_  (B_*N_)    // 131072 edges

// ---------------- scratch (device globals; no runtime allocation) ----------------
__device__ float g_nn [ (size_t)M_ * H_ ];   // LN(neighbor_feat)      268 MB
__device__ float g_mu [ (size_t)M_ * L_ ];   // mu                     134 MB
__device__ float g_lv [ (size_t)M_ * L_ ];   // logvar                 134 MB
__device__ float g_z  [ (size_t)M_ * L_ ];   // z (post-LN)            134 MB
__device__ float g_bias[M_];                 // bias-MLP output (accumulated)
__device__ float g_dot [M_];                 // qk . z per edge
__device__ float g_kl  [M_];                 // kl per edge
__device__ float g_qk  [B_ * L_];            // query @ k_w^T
__device__ float g_qkb [B_];                 // query . k_b
__device__ float g_ctx [B_ * L_];            // sum_n w_n z_n
__device__ float g_sw  [B_];                 // sum_n w_n
__device__ float g_klsum;
__device__ float g_nmsum;

// ---------------- block-wide sum (blockDim.x == 256) ----------------
__device__ __forceinline__ float blockSum(float v){
    __shared__ float red[8];
    int lane = threadIdx.x & 31, w = threadIdx.x >> 5;
    #pragma unroll
    for (int o = 16; o; o >>= 1) v += __shfl_xor_sync(0xffffffffu, v, o);
    if (lane == 0) red[w] = v;
    __syncthreads();
    if (threadIdx.x < 32){
        float x = (threadIdx.x < 8) ? red[threadIdx.x] : 0.f;
        #pragma unroll
        for (int o = 4; o; o >>= 1) x += __shfl_xor_sync(0xffffffffu, x, o);
        if (threadIdx.x == 0) red[0] = x;
    }
    __syncthreads();
    float r = red[0];
    __syncthreads();
    return r;
}

// ---------------- K0: LayerNorm(neighbor_feat) + zero accumulators ----------------
__global__ void k0_ln(const float* __restrict__ neigh,
                      const float* __restrict__ pre_w, const float* __restrict__ pre_b){
    int row = blockIdx.x, t = threadIdx.x;           // 256 threads handle 512 elems
    const float* x = neigh + (size_t)row * H_;
    float a = x[t], b = x[t + 256];
    float mean = blockSum(a + b) * (1.f / 512.f);
    float da = a - mean, db = b - mean;
    float var = blockSum(da*da + db*db) * (1.f / 512.f);
    float inv = rsqrtf(var + 1e-5f);
    float* o = g_nn + (size_t)row * H_;
    o[t]       = da * inv * pre_w[t]       + pre_b[t];
    o[t + 256] = db * inv * pre_w[t + 256] + pre_b[t + 256];
    if (t == 0){
        g_bias[row] = 0.f;
        if (row == 0){ g_klsum = 0.f; g_nmsum = 0.f; }
    }
}

// ---------------- K1: query = self@q_w + q_b ; qk = query@k_w^T ; qkb = query.k_b ----
// 8 batch rows per block.
__global__ void k1_query(const float* __restrict__ self,
                         const float* __restrict__ q_w, const float* __restrict__ q_b,
                         const float* __restrict__ k_w, const float* __restrict__ k_b){
    __shared__ float s_self[8][H_];   // 16 KB
    __shared__ float s_q[8][L_];      //  8 KB
    int b0 = blockIdx.x * 8;
    int tid = threadIdx.x;
    for (int idx = tid; idx < 8 * H_; idx += 256){
        int r = idx >> 9, h = idx & 511;
        s_self[r][h] = self[(size_t)(b0 + r) * H_ + h];
    }
    __syncthreads();
    {   // query
        float acc[8] = {};
        for (int h = 0; h < H_; h++){
            float w = q_w[(size_t)h * L_ + tid];
            #pragma unroll
            for (int r = 0; r < 8; r++) acc[r] += s_self[r][h] * w;
        }
        float qb = q_b[tid];
        #pragma unroll
        for (int r = 0; r < 8; r++) s_q[r][tid] = acc[r] + qb;
    }
    __syncthreads();
    {   // qk[m] = sum_l q[l] * k_w[m,l]
        float acc[8] = {};
        for (int l = 0; l < L_; l++){
            float w = k_w[(size_t)tid * L_ + l];
            #pragma unroll
            for (int r = 0; r < 8; r++) acc[r] += s_q[r][l] * w;
        }
        #pragma unroll
        for (int r = 0; r < 8; r++) g_qk[(size_t)(b0 + r) * L_ + tid] = acc[r];
    }
    // qkb: warp w handles row w
    int w = tid >> 5, lane = tid & 31;
    float p = 0.f;
    for (int l = lane; l < L_; l += 32) p += s_q[w][l] * k_b[l];
    #pragma unroll
    for (int o = 16; o; o >>= 1) p += __shfl_xor_sync(0xffffffffu, p, o);
    if (lane == 0) g_qkb[b0 + w] = p;
}

// ---------------- K2: SGEMM  [M_ x 512] @ [512 x Ncols] ----------------
// MODE 0: A = g_nn, C = g_mu (+mu_b)
// MODE 1: A = g_nn, C = g_lv (+lv_b)
// MODE 2: A = |self - neigh|, epilogue = relu(. + bm1_b) . bm2_w  -> atomicAdd g_bias
#define BM 128
#define BN 128
#define BK 16

template<int MODE>
__global__ void k2_gemm(const float* __restrict__ Bw, const float* __restrict__ biasv,
                        const float* __restrict__ bm2w,
                        const float* __restrict__ self, const float* __restrict__ neigh,
                        int Ncols){
    __shared__ float As[BK][BM + 1];   // +1 pad: conflict-free transpose store
    __shared__ float Bs[BK][BN];
    int m0 = blockIdx.x * BM;
    int n0 = blockIdx.y * BN;
    int tid = threadIdx.x;
    int tx = tid & 15, ty = tid >> 4;
    float acc[8][8] = {};

    for (int k0 = 0; k0 < H_; k0 += BK){
        #pragma unroll
        for (int i = 0; i < 8; i++){
            int idx = i * 256 + tid;
            int ar = idx >> 4, ac = idx & 15;
            int grow = m0 + ar, gcol = k0 + ac;
            float v;
            if (MODE < 2) v = g_nn[(size_t)grow * H_ + gcol];
            else          v = fabsf(self[(size_t)(grow >> 6) * H_ + gcol]
                                    - neigh[(size_t)grow * H_ + gcol]);
            As[ac][ar] = v;
        }
        #pragma unroll
        for (int i = 0; i < 8; i++){
            int idx = i * 256 + tid;
            int br = idx >> 7, bc = idx & 127;
            Bs[br][bc] = Bw[(size_t)(k0 + br) * Ncols + n0 + bc];
        }
        __syncthreads();
        #pragma unroll
        for (int kk = 0; kk < BK; kk++){
            float ra[8], rb[8];
            #pragma unroll
            for (int i = 0; i < 8; i++) ra[i] = As[kk][ty * 8 + i];
            #pragma unroll
            for (int j = 0; j < 8; j++) rb[j] = Bs[kk][tx * 8 + j];
            #pragma unroll
            for (int i = 0; i < 8; i++)
                #pragma unroll
                for (int j = 0; j < 8; j++)
                    acc[i][j] += ra[i] * rb[j];
        }
        __syncthreads();
    }

    if (MODE == 2){
        __shared__ float brow[BM];
        for (int i = tid; i < BM; i += 256) brow[i] = 0.f;
        __syncthreads();
        #pragma unroll
        for (int i = 0; i < 8; i++){
            float rp = 0.f;
            #pragma unroll
            for (int j = 0; j < 8; j++){
                int c = n0 + tx * 8 + j;
                float h = acc[i][j] + biasv[c];
                h = fmaxf(h, 0.f);
                rp += h * bm2w[c];
            }
            atomicAdd(&brow[ty * 8 + i], rp);
        }
        __syncthreads();
        for (int i = tid; i < BM; i += 256)
            atomicAdd(&g_bias[m0 + i], brow[i]);
    } else {
        float* C = (MODE == 0) ? g_mu : g_lv;
        #pragma unroll
        for (int i = 0; i < 8; i++){
            int r = m0 + ty * 8 + i;
            #pragma unroll
            for (int j = 0; j < 8; j++){
                int c = n0 + tx * 8 + j;
                C[(size_t)r * L_ + c] = acc[i][j] + biasv[c];
            }
        }
    }
}

// ---------------- K3: z = LN(mu + eps*exp(lv/2)) ; kl row ; qk.z dot ----------------
__global__ void k3_z(const float* __restrict__ eps,
                     const float* __restrict__ post_w, const float* __restrict__ post_b){
    int row = blockIdx.x, t = threadIdx.x;       // 256 threads == L_
    size_t o = (size_t)row * L_ + t;
    float mu = g_mu[o], lv = g_lv[o];
    float zp = mu + eps[o] * expf(0.5f * lv);
    float mean = blockSum(zp) * (1.f / 256.f);
    float d = zp - mean;
    float var = blockSum(d * d) * (1.f / 256.f);
    float z = d * rsqrtf(var + 1e-5f) * post_w[t] + post_b[t];
    g_z[o] = z;
    int b = row >> 6;
    float dot = blockSum(g_qk[(size_t)b * L_ + t] * z);
    float kl  = blockSum(1.f + lv - mu * mu - expf(lv));
    if (t == 0){ g_dot[row] = dot; g_kl[row] = -0.5f * kl; }
}

// ---------------- K4: logits / softmax / context aggregation ----------------
__global__ void k4_attn(const float* __restrict__ trust, const float* __restrict__ comm,
                        const float* __restrict__ bm2_b){
    int b = blockIdx.x, t = threadIdx.x;
    __shared__ float s_lg[N_], s_nm[N_], s_w[N_];
    if (t < N_){
        int row = b * N_ + t;
        float nm = comm[row];
        s_nm[t] = nm;
        float lg;
        if (nm < 0.5f) lg = -1e9f;
        else lg = (g_dot[row] + g_qkb[b]) * 0.0625f   // 1/sqrt(256)
                  - (g_bias[row] + bm2_b[0])
                  + logf(trust[row] + 1e-6f);
        s_lg[t] = lg;
    }
    __syncthreads();
    if (t == 0){
        float mx = -3.4e38f;
        for (int n = 0; n < N_; n++) mx = fmaxf(mx, s_lg[n]);
        float se = 0.f;
        for (int n = 0; n < N_; n++) se += expf(s_lg[n] - mx);
        float wsum = 0.f;
        for (int n = 0; n < N_; n++){
            float w = expf(s_lg[n] - mx) / se * s_nm[n];
            s_w[n] = w; wsum += w;
        }
        float denom = fmaxf(wsum, 1e-6f);
        float tot = 0.f, klp = 0.f, nmp = 0.f;
        for (int n = 0; n < N_; n++){
            s_w[n] /= denom;
            tot += s_w[n];
            klp += g_kl[b * N_ + n] * s_nm[n];
            nmp += s_nm[n];
        }
        g_sw[b] = tot;
        atomicAdd(&g_klsum, klp);
        atomicAdd(&g_nmsum, nmp);
    }
    __syncthreads();
    float acc = 0.f;
    const float* zb = g_z + (size_t)b * N_ * L_;
    for (int n = 0; n < N_; n++) acc += s_w[n] * zb[n * L_ + t];
    g_ctx[(size_t)b * L_ + t] = acc;
}

// ---------------- K5: context@v_w -> @out_w -> comm_feat (16 rows / block) ----------
__global__ void k5_out(const float* __restrict__ v_w, const float* __restrict__ v_b,
                       const float* __restrict__ out_w, const float* __restrict__ out_b,
                       float* __restrict__ out){
    __shared__ float s_cx[16][L_];   // 16 KB
    __shared__ float s_c2[16][L_];   // 16 KB
    __shared__ float s_sw[16];
    int b0 = blockIdx.x * 16;
    int tid = threadIdx.x;
    for (int idx = tid; idx < 16 * L_; idx += 256){
        int r = idx >> 8, l = idx & 255;
        s_cx[r][l] = g_ctx[(size_t)(b0 + r) * L_ + l];
    }
    if (tid < 16) s_sw[tid] = g_sw[b0 + tid];
    __syncthreads();
    {
        float acc[16] = {};
        for (int l = 0; l < L_; l++){
            float w = v_w[(size_t)l * L_ + tid];
            #pragma unroll
            for (int r = 0; r < 16; r++) acc[r] += s_cx[r][l] * w;
        }
        float vb = v_b[tid];
        #pragma unroll
        for (int r = 0; r < 16; r++) s_c2[r][tid] = acc[r] + vb * s_sw[r];
    }
    __syncthreads();
    for (int hh = 0; hh < 2; hh++){
        int h = tid + hh * 256;
        float acc[16] = {};
        for (int l = 0; l < L_; l++){
            float w = out_w[(size_t)l * H_ + h];
            #pragma unroll
            for (int r = 0; r < 16; r++) acc[r] += s_c2[r][l] * w;
        }
        float ob = out_b[h];
        #pragma unroll
        for (int r = 0; r < 16; r++) out[(size_t)(b0 + r) * H_ + h] = acc[r] + ob;
    }
}

// ---------------- K6: kl scalars ----------------
__global__ void k6_kl(float* __restrict__ out){
    float klraw = g_klsum / fmaxf(g_nmsum, 1.f);
    out[(size_t)B_ * H_]     = 0.01f * klraw;   // KL_BETA * kl_raw
    out[(size_t)B_ * H_ + 1] = klraw;
}

// ---------------- launch ----------------
extern "C" void kernel_launch(void* const* d_in, const int* in_sizes, int n_in,
                              void* d_out, int out_size){
    const float* self   = (const float*)d_in[0];
    const float* neigh  = (const float*)d_in[1];
    const float* trust  = (const float*)d_in[2];
    const float* comm   = (const float*)d_in[3];
    const float* eps    = (const float*)d_in[4];
    const float* pre_w  = (const float*)d_in[5];
    const float* pre_b  = (const float*)d_in[6];
    const float* mu_w   = (const float*)d_in[7];
    const float* mu_b   = (const float*)d_in[8];
    const float* lv_w   = (const float*)d_in[9];
    const float* lv_b   = (const float*)d_in[10];
    const float* post_w = (const float*)d_in[11];
    const float* post_b = (const float*)d_in[12];
    const float* q_w    = (const float*)d_in[13];
    const float* q_b    = (const float*)d_in[14];
    const float* k_w    = (const float*)d_in[15];
    const float* k_b    = (const float*)d_in[16];
    const float* v_w    = (const float*)d_in[17];
    const float* v_b    = (const float*)d_in[18];
    const float* out_w  = (const float*)d_in[19];
    const float* out_b  = (const float*)d_in[20];
    const float* bm1_w  = (const float*)d_in[21];
    const float* bm1_b  = (const float*)d_in[22];
    const float* bm2_w  = (const float*)d_in[23];
    const float* bm2_b  = (const float*)d_in[24];
    float* out = (float*)d_out;

    k0_ln<<<M_, 256>>>(neigh, pre_w, pre_b);
    k1_query<<<B_ / 8, 256>>>(self, q_w, q_b, k_w, k_b);
    k2_gemm<0><<<dim3(M_ / BM, L_ / BN), 256>>>(mu_w, mu_b, nullptr, nullptr, nullptr, L_);
    k2_gemm<1><<<dim3(M_ / BM, L_ / BN), 256>>>(lv_w, lv_b, nullptr, nullptr, nullptr, L_);
    k2_gemm<2><<<dim3(M_ / BM, H_ / BN), 256>>>(bm1_w, bm1_b, bm2_w, self, neigh, H_);
    k3_z<<<M_, 256>>>(eps, post_w, post_b);
    k4_attn<<<B_, 256>>>(trust, comm, bm2_b);
    k5_out<<<B_ / 16, 256>>>(v_w, v_b, out_w, out_b, out);
    k6_kl<<<1, 1>>>(out);
}

// round 4
// speedup vs baseline: 2.2399x; 2.2399x over previous
#include <cuda_runtime.h>
#include <math.h>
#include <stdint.h>

#define B_  2048
#define N_  64
#define H_  512
#define L_  256
#define M_  (B_*N_)    // 131072 edges

// ---------------- scratch ----------------
__device__ float g_mu [ (size_t)M_ * L_ ];
__device__ float g_lv [ (size_t)M_ * L_ ];
__device__ float g_z  [ (size_t)M_ * L_ ];
__device__ float g_mean[M_];
__device__ float g_rstd[M_];
__device__ float g_bias[M_];
__device__ float g_dot [M_];
__device__ float g_kl  [M_];
__device__ float g_qk  [B_ * L_];
__device__ float g_qkb [B_];
__device__ float g_ctx [B_ * L_];
__device__ float g_sw  [B_];
__device__ float g_klsum;
__device__ float g_nmsum;

// ---------------- helpers ----------------
__device__ __forceinline__ uint32_t f2tf(float x){
    uint32_t u; asm("cvt.rna.tf32.f32 %0, %1;" : "=r"(u) : "f"(x)); return u;
}
__device__ __forceinline__ void mma_tf32(float4& d, const uint32_t a[4], const uint32_t b[2]){
    asm volatile("mma.sync.aligned.m16n8k8.row.col.f32.tf32.tf32.f32 "
        "{%0,%1,%2,%3}, {%4,%5,%6,%7}, {%8,%9}, {%0,%1,%2,%3};\n"
        : "+f"(d.x), "+f"(d.y), "+f"(d.z), "+f"(d.w)
        : "r"(a[0]), "r"(a[1]), "r"(a[2]), "r"(a[3]), "r"(b[0]), "r"(b[1]));
}

__device__ __forceinline__ float blockSum(float v){
    __shared__ float red[8];
    int lane = threadIdx.x & 31, w = threadIdx.x >> 5;
    #pragma unroll
    for (int o = 16; o; o >>= 1) v += __shfl_xor_sync(0xffffffffu, v, o);
    if (lane == 0) red[w] = v;
    __syncthreads();
    if (threadIdx.x < 32){
        float x = (threadIdx.x < 8) ? red[threadIdx.x] : 0.f;
        #pragma unroll
        for (int o = 4; o; o >>= 1) x += __shfl_xor_sync(0xffffffffu, x, o);
        if (threadIdx.x == 0) red[0] = x;
    }
    __syncthreads();
    float r = red[0];
    __syncthreads();
    return r;
}

// ---------------- K0: per-row LN stats (warp per row) + zero accumulators --------
__global__ void k0_stats(const float* __restrict__ neigh){
    int row = blockIdx.x * 8 + (threadIdx.x >> 5);
    int lane = threadIdx.x & 31;
    const float4* x = (const float4*)(neigh + (size_t)row * H_);
    float s = 0.f, ss = 0.f;
    #pragma unroll
    for (int i = 0; i < 4; i++){
        float4 v = x[lane + 32 * i];
        s  += v.x + v.y + v.z + v.w;
        ss += v.x*v.x + v.y*v.y + v.z*v.z + v.w*v.w;
    }
    #pragma unroll
    for (int o = 16; o; o >>= 1){
        s  += __shfl_xor_sync(0xffffffffu, s, o);
        ss += __shfl_xor_sync(0xffffffffu, ss, o);
    }
    if (lane == 0){
        float mean = s * (1.f / 512.f);
        float var  = ss * (1.f / 512.f) - mean * mean;
        g_mean[row] = mean;
        g_rstd[row] = rsqrtf(var + 1e-5f);
        g_bias[row] = 0.f;
        if (row == 0){ g_klsum = 0.f; g_nmsum = 0.f; }
    }
}

// ---------------- K1: query = self@q_w + q_b ; qk = query@k_w^T ; qkb = query.k_b --
__global__ void k1_query(const float* __restrict__ self,
                         const float* __restrict__ q_w, const float* __restrict__ q_b,
                         const float* __restrict__ k_w, const float* __restrict__ k_b){
    __shared__ float s_self[8][H_];
    __shared__ float s_q[8][L_];
    int b0 = blockIdx.x * 8;
    int tid = threadIdx.x;
    for (int idx = tid; idx < 8 * H_; idx += 256){
        int r = idx >> 9, h = idx & 511;
        s_self[r][h] = self[(size_t)(b0 + r) * H_ + h];
    }
    __syncthreads();
    {
        float acc[8] = {};
        for (int h = 0; h < H_; h++){
            float w = q_w[(size_t)h * L_ + tid];
            #pragma unroll
            for (int r = 0; r < 8; r++) acc[r] += s_self[r][h] * w;
        }
        float qb = q_b[tid];
        #pragma unroll
        for (int r = 0; r < 8; r++) s_q[r][tid] = acc[r] + qb;
    }
    __syncthreads();
    {
        float acc[8] = {};
        for (int l = 0; l < L_; l++){
            float w = k_w[(size_t)tid * L_ + l];
            #pragma unroll
            for (int r = 0; r < 8; r++) acc[r] += s_q[r][l] * w;
        }
        #pragma unroll
        for (int r = 0; r < 8; r++) g_qk[(size_t)(b0 + r) * L_ + tid] = acc[r];
    }
    int w = tid >> 5, lane = tid & 31;
    float p = 0.f;
    for (int l = lane; l < L_; l += 32) p += s_q[w][l] * k_b[l];
    #pragma unroll
    for (int o = 16; o; o >>= 1) p += __shfl_xor_sync(0xffffffffu, p, o);
    if (lane == 0) g_qkb[b0 + w] = p;
}

// ---------------- K2: tf32 tensor-core GEMM ----------------
// MODE 0: A = LN(neigh) on the fly; grid.y 0,1 -> mu cols [0/128..); 2,3 -> lv
// MODE 1: A = |self - neigh|;      grid.y 0..3 -> bm1 cols; epilogue relu.bm2 row-reduce
#define BMg 128
#define BNg 128
#define BKg 16

template<int MODE>
__global__ __launch_bounds__(256)
void gemm_tf32(const float* __restrict__ neigh, const float* __restrict__ self,
               const float* __restrict__ pre_w, const float* __restrict__ pre_b,
               const float* __restrict__ Bw0, const float* __restrict__ bias0,
               const float* __restrict__ Bw1, const float* __restrict__ bias1,
               const float* __restrict__ bm2w){
    __shared__ __align__(16) uint32_t As[BKg][BMg + 4];
    __shared__ __align__(16) uint32_t Bs[BKg][BNg + 4];
    __shared__ float s_mean[BMg], s_rstd[BMg];
    __shared__ float s_prew[H_], s_preb[H_];

    int m0 = blockIdx.x * BMg;
    int yy = blockIdx.y;
    int tid = threadIdx.x;
    int lane = tid & 31, w = tid >> 5;

    const float* Bw; const float* biasv; int n0, Ncols;
    if (MODE == 0){
        if (yy < 2){ Bw = Bw0; biasv = bias0; n0 = yy * 128; }
        else       { Bw = Bw1; biasv = bias1; n0 = (yy - 2) * 128; }
        Ncols = L_;
    } else {
        Bw = Bw0; biasv = bias0; n0 = yy * 128; Ncols = H_;
    }

    if (MODE == 0){
        for (int i = tid; i < BMg; i += 256){
            s_mean[i] = g_mean[m0 + i]; s_rstd[i] = g_rstd[m0 + i];
        }
        for (int i = tid; i < H_; i += 256){
            s_prew[i] = pre_w[i]; s_preb[i] = pre_b[i];
        }
        __syncthreads();
    }

    int am = tid >> 2;            // 0..63
    int ak = (tid & 3) * 4;       // 0,4,8,12
    int bn4 = lane * 4;
    int wm = (w & 3) * 32;
    int wn = (w >> 2) * 64;

    float4 acc[2][8];
    #pragma unroll
    for (int i = 0; i < 2; i++)
        #pragma unroll
        for (int j = 0; j < 8; j++) acc[i][j] = make_float4(0.f, 0.f, 0.f, 0.f);

    for (int k0 = 0; k0 < H_; k0 += BKg){
        #pragma unroll
        for (int half = 0; half < 2; half++){
            int m = am + half * 64;
            float4 v = *(const float4*)(neigh + (size_t)(m0 + m) * H_ + k0 + ak);
            float x0, x1, x2, x3;
            if (MODE == 0){
                float mn = s_mean[m], rs = s_rstd[m];
                x0 = (v.x - mn) * rs * s_prew[k0+ak+0] + s_preb[k0+ak+0];
                x1 = (v.y - mn) * rs * s_prew[k0+ak+1] + s_preb[k0+ak+1];
                x2 = (v.z - mn) * rs * s_prew[k0+ak+2] + s_preb[k0+ak+2];
                x3 = (v.w - mn) * rs * s_prew[k0+ak+3] + s_preb[k0+ak+3];
            } else {
                int bb = (m0 + m) >> 6;
                float4 sv = *(const float4*)(self + (size_t)bb * H_ + k0 + ak);
                x0 = fabsf(sv.x - v.x); x1 = fabsf(sv.y - v.y);
                x2 = fabsf(sv.z - v.z); x3 = fabsf(sv.w - v.w);
            }
            As[ak+0][m] = f2tf(x0); As[ak+1][m] = f2tf(x1);
            As[ak+2][m] = f2tf(x2); As[ak+3][m] = f2tf(x3);
        }
        #pragma unroll
        for (int half = 0; half < 2; half++){
            int kk = w + half * 8;
            float4 v = *(const float4*)(Bw + (size_t)(k0 + kk) * Ncols + n0 + bn4);
            Bs[kk][bn4+0] = f2tf(v.x); Bs[kk][bn4+1] = f2tf(v.y);
            Bs[kk][bn4+2] = f2tf(v.z); Bs[kk][bn4+3] = f2tf(v.w);
        }
        __syncthreads();
        #pragma unroll
        for (int ks = 0; ks < 2; ks++){
            int kb = ks * 8;
            uint32_t af[2][4];
            #pragma unroll
            for (int mi = 0; mi < 2; mi++){
                int r = wm + mi * 16 + (lane >> 2);
                int c = kb + (lane & 3);
                af[mi][0] = As[c][r];
                af[mi][1] = As[c][r + 8];
                af[mi][2] = As[c + 4][r];
                af[mi][3] = As[c + 4][r + 8];
            }
            #pragma unroll
            for (int ni = 0; ni < 8; ni++){
                int n = wn + ni * 8 + (lane >> 2);
                uint32_t bf[2];
                bf[0] = Bs[kb + (lane & 3)][n];
                bf[1] = Bs[kb + (lane & 3) + 4][n];
                #pragma unroll
                for (int mi = 0; mi < 2; mi++) mma_tf32(acc[mi][ni], af[mi], bf);
            }
        }
        __syncthreads();
    }

    if (MODE == 0){
        float* C = (yy < 2) ? g_mu : g_lv;
        #pragma unroll
        for (int mi = 0; mi < 2; mi++){
            int r0 = m0 + wm + mi * 16 + (lane >> 2);
            #pragma unroll
            for (int ni = 0; ni < 8; ni++){
                int c = n0 + wn + ni * 8 + 2 * (lane & 3);
                float b0 = biasv[c], b1 = biasv[c + 1];
                float4 a = acc[mi][ni];
                *(float2*)(C + (size_t)r0 * L_ + c)       = make_float2(a.x + b0, a.y + b1);
                *(float2*)(C + (size_t)(r0 + 8) * L_ + c) = make_float2(a.z + b0, a.w + b1);
            }
        }
    } else {
        __shared__ float brow[BMg];
        for (int i = tid; i < BMg; i += 256) brow[i] = 0.f;
        __syncthreads();
        #pragma unroll
        for (int mi = 0; mi < 2; mi++){
            float s0 = 0.f, s1 = 0.f;
            #pragma unroll
            for (int ni = 0; ni < 8; ni++){
                int c = n0 + wn + ni * 8 + 2 * (lane & 3);
                float w0 = bm2w[c], w1 = bm2w[c + 1];
                float b0 = biasv[c], b1 = biasv[c + 1];
                float4 a = acc[mi][ni];
                s0 += fmaxf(a.x + b0, 0.f) * w0 + fmaxf(a.y + b1, 0.f) * w1;
                s1 += fmaxf(a.z + b0, 0.f) * w0 + fmaxf(a.w + b1, 0.f) * w1;
            }
            s0 += __shfl_xor_sync(0xffffffffu, s0, 1);
            s0 += __shfl_xor_sync(0xffffffffu, s0, 2);
            s1 += __shfl_xor_sync(0xffffffffu, s1, 1);
            s1 += __shfl_xor_sync(0xffffffffu, s1, 2);
            if ((lane & 3) == 0){
                atomicAdd(&brow[wm + mi * 16 + (lane >> 2)], s0);
                atomicAdd(&brow[wm + mi * 16 + (lane >> 2) + 8], s1);
            }
        }
        __syncthreads();
        for (int i = tid; i < BMg; i += 256)
            atomicAdd(&g_bias[m0 + i], brow[i]);
    }
}

// ---------------- K3: z = LN(mu + eps*exp(lv/2)) ; kl ; qk.z ----------------
__global__ void k3_z(const float* __restrict__ eps,
                     const float* __restrict__ post_w, const float* __restrict__ post_b){
    int row = blockIdx.x, t = threadIdx.x;
    size_t o = (size_t)row * L_ + t;
    float mu = g_mu[o], lv = g_lv[o];
    float zp = mu + eps[o] * expf(0.5f * lv);
    float mean = blockSum(zp) * (1.f / 256.f);
    float d = zp - mean;
    float var = blockSum(d * d) * (1.f / 256.f);
    float z = d * rsqrtf(var + 1e-5f) * post_w[t] + post_b[t];
    g_z[o] = z;
    int b = row >> 6;
    float dot = blockSum(g_qk[(size_t)b * L_ + t] * z);
    float kl  = blockSum(1.f + lv - mu * mu - expf(lv));
    if (t == 0){ g_dot[row] = dot; g_kl[row] = -0.5f * kl; }
}

// ---------------- K4: logits / softmax / context ----------------
__global__ void k4_attn(const float* __restrict__ trust, const float* __restrict__ comm,
                        const float* __restrict__ bm2_b){
    int b = blockIdx.x, t = threadIdx.x;
    __shared__ float s_lg[N_], s_nm[N_], s_w[N_];
    if (t < N_){
        int row = b * N_ + t;
        float nm = comm[row];
        s_nm[t] = nm;
        float lg;
        if (nm < 0.5f) lg = -1e9f;
        else lg = (g_dot[row] + g_qkb[b]) * 0.0625f
                  - (g_bias[row] + bm2_b[0])
                  + logf(trust[row] + 1e-6f);
        s_lg[t] = lg;
    }
    __syncthreads();
    if (t == 0){
        float mx = -3.4e38f;
        for (int n = 0; n < N_; n++) mx = fmaxf(mx, s_lg[n]);
        float se = 0.f;
        for (int n = 0; n < N_; n++) se += expf(s_lg[n] - mx);
        float wsum = 0.f;
        for (int n = 0; n < N_; n++){
            float w = expf(s_lg[n] - mx) / se * s_nm[n];
            s_w[n] = w; wsum += w;
        }
        float denom = fmaxf(wsum, 1e-6f);
        float tot = 0.f, klp = 0.f, nmp = 0.f;
        for (int n = 0; n < N_; n++){
            s_w[n] /= denom;
            tot += s_w[n];
            klp += g_kl[b * N_ + n] * s_nm[n];
            nmp += s_nm[n];
        }
        g_sw[b] = tot;
        atomicAdd(&g_klsum, klp);
        atomicAdd(&g_nmsum, nmp);
    }
    __syncthreads();
    float acc = 0.f;
    const float* zb = g_z + (size_t)b * N_ * L_;
    for (int n = 0; n < N_; n++) acc += s_w[n] * zb[n * L_ + t];
    g_ctx[(size_t)b * L_ + t] = acc;
}

// ---------------- K5: context@v_w -> @out_w -> comm_feat ----------------
__global__ void k5_out(const float* __restrict__ v_w, const float* __restrict__ v_b,
                       const float* __restrict__ out_w, const float* __restrict__ out_b,
                       float* __restrict__ out){
    __shared__ float s_cx[16][L_];
    __shared__ float s_c2[16][L_];
    __shared__ float s_sw[16];
    int b0 = blockIdx.x * 16;
    int tid = threadIdx.x;
    for (int idx = tid; idx < 16 * L_; idx += 256){
        int r = idx >> 8, l = idx & 255;
        s_cx[r][l] = g_ctx[(size_t)(b0 + r) * L_ + l];
    }
    if (tid < 16) s_sw[tid] = g_sw[b0 + tid];
    __syncthreads();
    {
        float acc[16] = {};
        for (int l = 0; l < L_; l++){
            float w = v_w[(size_t)l * L_ + tid];
            #pragma unroll
            for (int r = 0; r < 16; r++) acc[r] += s_cx[r][l] * w;
        }
        float vb = v_b[tid];
        #pragma unroll
        for (int r = 0; r < 16; r++) s_c2[r][tid] = acc[r] + vb * s_sw[r];
    }
    __syncthreads();
    for (int hh = 0; hh < 2; hh++){
        int h = tid + hh * 256;
        float acc[16] = {};
        for (int l = 0; l < L_; l++){
            float w = out_w[(size_t)l * H_ + h];
            #pragma unroll
            for (int r = 0; r < 16; r++) acc[r] += s_c2[r][l] * w;
        }
        float ob = out_b[h];
        #pragma unroll
        for (int r = 0; r < 16; r++) out[(size_t)(b0 + r) * H_ + h] = acc[r] + ob;
    }
}

// ---------------- K6: kl scalars ----------------
__global__ void k6_kl(float* __restrict__ out){
    float klraw = g_klsum / fmaxf(g_nmsum, 1.f);
    out[(size_t)B_ * H_]     = 0.01f * klraw;
    out[(size_t)B_ * H_ + 1] = klraw;
}

// ---------------- launch ----------------
extern "C" void kernel_launch(void* const* d_in, const int* in_sizes, int n_in,
                              void* d_out, int out_size){
    const float* self   = (const float*)d_in[0];
    const float* neigh  = (const float*)d_in[1];
    const float* trust  = (const float*)d_in[2];
    const float* comm   = (const float*)d_in[3];
    const float* eps    = (const float*)d_in[4];
    const float* pre_w  = (const float*)d_in[5];
    const float* pre_b  = (const float*)d_in[6];
    const float* mu_w   = (const float*)d_in[7];
    const float* mu_b   = (const float*)d_in[8];
    const float* lv_w   = (const float*)d_in[9];
    const float* lv_b   = (const float*)d_in[10];
    const float* post_w = (const float*)d_in[11];
    const float* post_b = (const float*)d_in[12];
    const float* q_w    = (const float*)d_in[13];
    const float* q_b    = (const float*)d_in[14];
    const float* k_w    = (const float*)d_in[15];
    const float* k_b    = (const float*)d_in[16];
    const float* v_w    = (const float*)d_in[17];
    const float* v_b    = (const float*)d_in[18];
    const float* out_w  = (const float*)d_in[19];
    const float* out_b  = (const float*)d_in[20];
    const float* bm1_w  = (const float*)d_in[21];
    const float* bm1_b  = (const float*)d_in[22];
    const float* bm2_w  = (const float*)d_in[23];
    const float* bm2_b  = (const float*)d_in[24];
    float* out = (float*)d_out;

    k0_stats<<<M_ / 8, 256>>>(neigh);
    k1_query<<<B_ / 8, 256>>>(self, q_w, q_b, k_w, k_b);
    gemm_tf32<0><<<dim3(M_ / BMg, 4), 256>>>(neigh, nullptr, pre_w, pre_b,
                                             mu_w, mu_b, lv_w, lv_b, nullptr);
    gemm_tf32<1><<<dim3(M_ / BMg, 4), 256>>>(neigh, self, nullptr, nullptr,
                                             bm1_w, bm1_b, nullptr, nullptr, bm2_w);
    k3_z<<<M_, 256>>>(eps, post_w, post_b);
    k4_attn<<<B_, 256>>>(trust, comm, bm2_b);
    k5_out<<<B_ / 16, 256>>>(v_w, v_b, out_w, out_b, out);
    k6_kl<<<1, 1>>>(out);
}

// round 5
// speedup vs baseline: 2.7144x; 1.2118x over previous
#include <cuda_runtime.h>
#include <math.h>
#include <stdint.h>

#define B_  2048
#define N_  64
#define H_  512
#define L_  256
#define M_  (B_*N_)    // 131072 edges

// ---------------- scratch ----------------
__device__ float g_mu [ (size_t)M_ * L_ ];
__device__ float g_lv [ (size_t)M_ * L_ ];
__device__ float g_mean[M_];
__device__ float g_rstd[M_];
__device__ float g_bias[M_];
__device__ float g_qk  [B_ * L_];
__device__ float g_qkb [B_];
__device__ float g_ctx [B_ * L_];
__device__ float g_sw  [B_];
__device__ float g_klsum;
__device__ float g_nmsum;

// ---------------- helpers ----------------
__device__ __forceinline__ uint32_t f2tf(float x){
    uint32_t u; asm("cvt.rna.tf32.f32 %0, %1;" : "=r"(u) : "f"(x)); return u;
}
__device__ __forceinline__ void mma_tf32(float4& d, const uint32_t a[4], const uint32_t b[2]){
    asm volatile("mma.sync.aligned.m16n8k8.row.col.f32.tf32.tf32.f32 "
        "{%0,%1,%2,%3}, {%4,%5,%6,%7}, {%8,%9}, {%0,%1,%2,%3};\n"
        : "+f"(d.x), "+f"(d.y), "+f"(d.z), "+f"(d.w)
        : "r"(a[0]), "r"(a[1]), "r"(a[2]), "r"(a[3]), "r"(b[0]), "r"(b[1]));
}
__device__ __forceinline__ float warpSum(float v){
    #pragma unroll
    for (int o = 16; o; o >>= 1) v += __shfl_xor_sync(0xffffffffu, v, o);
    return v;
}

// ---------------- K0: per-row LN stats (warp per row) + zero accumulators --------
__global__ void k0_stats(const float* __restrict__ neigh){
    int row = blockIdx.x * 8 + (threadIdx.x >> 5);
    int lane = threadIdx.x & 31;
    const float4* x = (const float4*)(neigh + (size_t)row * H_);
    float s = 0.f, ss = 0.f;
    #pragma unroll
    for (int i = 0; i < 4; i++){
        float4 v = x[lane + 32 * i];
        s  += v.x + v.y + v.z + v.w;
        ss += v.x*v.x + v.y*v.y + v.z*v.z + v.w*v.w;
    }
    s = warpSum(s); ss = warpSum(ss);
    if (lane == 0){
        float mean = s * (1.f / 512.f);
        float var  = ss * (1.f / 512.f) - mean * mean;
        g_mean[row] = mean;
        g_rstd[row] = rsqrtf(var + 1e-5f);
        g_bias[row] = 0.f;
        if (row == 0){ g_klsum = 0.f; g_nmsum = 0.f; }
    }
}

// ---------------- K1: query = self@q_w + q_b ; qk = query@k_w^T ; qkb = query.k_b --
__global__ void k1_query(const float* __restrict__ self,
                         const float* __restrict__ q_w, const float* __restrict__ q_b,
                         const float* __restrict__ k_w, const float* __restrict__ k_b){
    __shared__ float s_self[8][H_];
    __shared__ float s_q[8][L_];
    int b0 = blockIdx.x * 8;
    int tid = threadIdx.x;
    for (int idx = tid; idx < 8 * H_; idx += 256){
        int r = idx >> 9, h = idx & 511;
        s_self[r][h] = self[(size_t)(b0 + r) * H_ + h];
    }
    __syncthreads();
    {
        float acc[8] = {};
        for (int h = 0; h < H_; h++){
            float w = q_w[(size_t)h * L_ + tid];
            #pragma unroll
            for (int r = 0; r < 8; r++) acc[r] += s_self[r][h] * w;
        }
        float qb = q_b[tid];
        #pragma unroll
        for (int r = 0; r < 8; r++) s_q[r][tid] = acc[r] + qb;
    }
    __syncthreads();
    {
        float acc[8] = {};
        for (int l = 0; l < L_; l++){
            float w = k_w[(size_t)tid * L_ + l];
            #pragma unroll
            for (int r = 0; r < 8; r++) acc[r] += s_q[r][l] * w;
        }
        #pragma unroll
        for (int r = 0; r < 8; r++) g_qk[(size_t)(b0 + r) * L_ + tid] = acc[r];
    }
    int w = tid >> 5, lane = tid & 31;
    float p = 0.f;
    for (int l = lane; l < L_; l += 32) p += s_q[w][l] * k_b[l];
    p = warpSum(p);
    if (lane == 0) g_qkb[b0 + w] = p;
}

// ---------------- K2: pipelined tf32 tensor-core GEMM ----------------
// MODE 0: A = LN(neigh) on the fly; grid.y 0,1 -> mu cols; 2,3 -> lv cols
// MODE 1: A = |self - neigh|;      grid.y 0..3 -> bm1 cols; epilogue relu.bm2
#define BMg 128
#define BNg 128
#define BKg 16
#define ASS (BKg + 4)    // As row stride (words): 20 -> conflict-free frag loads
#define BSS (BNg + 8)    // Bs row stride (words): 136 -> conflict-free frag loads

template<int MODE>
__global__ __launch_bounds__(256)
void gemm_tf32(const float* __restrict__ neigh, const float* __restrict__ self,
               const float* __restrict__ pre_w, const float* __restrict__ pre_b,
               const float* __restrict__ Bw0, const float* __restrict__ bias0,
               const float* __restrict__ Bw1, const float* __restrict__ bias1,
               const float* __restrict__ bm2w){
    __shared__ __align__(16) uint32_t As[2][BMg * ASS];   // A as [m][k], 2 stages
    __shared__ __align__(16) uint32_t Bs[2][BKg * BSS];   // B as [k][n], 2 stages
    __shared__ float s_mean[BMg], s_rstd[BMg];
    __shared__ float s_prew[(MODE == 0) ? H_ : 1];
    __shared__ float s_preb[(MODE == 0) ? H_ : 1];

    int m0 = blockIdx.x * BMg;
    int yy = blockIdx.y;
    int tid = threadIdx.x;
    int lane = tid & 31, w = tid >> 5;

    const float* Bw; const float* biasv; int n0, Ncols;
    if (MODE == 0){
        if (yy < 2){ Bw = Bw0; biasv = bias0; n0 = yy * 128; }
        else       { Bw = Bw1; biasv = bias1; n0 = (yy - 2) * 128; }
        Ncols = L_;
    } else {
        Bw = Bw0; biasv = bias0; n0 = yy * 128; Ncols = H_;
    }

    if (MODE == 0){
        for (int i = tid; i < BMg; i += 256){
            s_mean[i] = g_mean[m0 + i]; s_rstd[i] = g_rstd[m0 + i];
        }
        for (int i = tid; i < H_; i += 256){
            s_prew[i] = pre_w[i]; s_preb[i] = pre_b[i];
        }
        __syncthreads();
    }

    int am = tid >> 2;            // 0..63
    int ak = (tid & 3) * 4;       // 0,4,8,12
    int bn4 = lane * 4;
    int wm = (w & 3) * 32;
    int wn = (w >> 2) * 64;

    float4 acc[2][8];
    #pragma unroll
    for (int i = 0; i < 2; i++)
        #pragma unroll
        for (int j = 0; j < 8; j++) acc[i][j] = make_float4(0.f, 0.f, 0.f, 0.f);

    const int KT = H_ / BKg;     // 32
    float4 vA0, vA1, vB0, vB1, vS0, vS1;

    // ---- staged global loads for tile kt ----
    auto LDG = [&](int kt){
        int k0 = kt * BKg;
        vA0 = *(const float4*)(neigh + (size_t)(m0 + am) * H_ + k0 + ak);
        vA1 = *(const float4*)(neigh + (size_t)(m0 + am + 64) * H_ + k0 + ak);
        if (MODE == 1){
            vS0 = *(const float4*)(self + (size_t)((m0 + am) >> 6) * H_ + k0 + ak);
            vS1 = *(const float4*)(self + (size_t)((m0 + am + 64) >> 6) * H_ + k0 + ak);
        }
        vB0 = *(const float4*)(Bw + (size_t)(k0 + w) * Ncols + n0 + bn4);
        vB1 = *(const float4*)(Bw + (size_t)(k0 + w + 8) * Ncols + n0 + bn4);
    };
    // ---- transform + store to stage buf ----
    auto STS = [&](int buf, int kt){
        int k0 = kt * BKg;
        float x0, x1, x2, x3;
        if (MODE == 0){
            float mn = s_mean[am], rs = s_rstd[am];
            x0 = (vA0.x - mn) * rs * s_prew[k0+ak+0] + s_preb[k0+ak+0];
            x1 = (vA0.y - mn) * rs * s_prew[k0+ak+1] + s_preb[k0+ak+1];
            x2 = (vA0.z - mn) * rs * s_prew[k0+ak+2] + s_preb[k0+ak+2];
            x3 = (vA0.w - mn) * rs * s_prew[k0+ak+3] + s_preb[k0+ak+3];
        } else {
            x0 = fabsf(vS0.x - vA0.x); x1 = fabsf(vS0.y - vA0.y);
            x2 = fabsf(vS0.z - vA0.z); x3 = fabsf(vS0.w - vA0.w);
        }
        uint4 p0 = make_uint4(f2tf(x0), f2tf(x1), f2tf(x2), f2tf(x3));
        *(uint4*)&As[buf][am * ASS + ak] = p0;
        if (MODE == 0){
            float mn = s_mean[am + 64], rs = s_rstd[am + 64];
            x0 = (vA1.x - mn) * rs * s_prew[k0+ak+0] + s_preb[k0+ak+0];
            x1 = (vA1.y - mn) * rs * s_prew[k0+ak+1] + s_preb[k0+ak+1];
            x2 = (vA1.z - mn) * rs * s_prew[k0+ak+2] + s_preb[k0+ak+2];
            x3 = (vA1.w - mn) * rs * s_prew[k0+ak+3] + s_preb[k0+ak+3];
        } else {
            x0 = fabsf(vS1.x - vA1.x); x1 = fabsf(vS1.y - vA1.y);
            x2 = fabsf(vS1.z - vA1.z); x3 = fabsf(vS1.w - vA1.w);
        }
        uint4 p1 = make_uint4(f2tf(x0), f2tf(x1), f2tf(x2), f2tf(x3));
        *(uint4*)&As[buf][(am + 64) * ASS + ak] = p1;
        uint4 q0 = make_uint4(f2tf(vB0.x), f2tf(vB0.y), f2tf(vB0.z), f2tf(vB0.w));
        uint4 q1 = make_uint4(f2tf(vB1.x), f2tf(vB1.y), f2tf(vB1.z), f2tf(vB1.w));
        *(uint4*)&Bs[buf][w * BSS + bn4]       = q0;
        *(uint4*)&Bs[buf][(w + 8) * BSS + bn4] = q1;
    };

    LDG(0); STS(0, 0);
    __syncthreads();

    for (int kt = 0; kt < KT; kt++){
        int cur = kt & 1;
        if (kt + 1 < KT) LDG(kt + 1);
        #pragma unroll
        for (int ks = 0; ks < 2; ks++){
            int kb = ks * 8;
            uint32_t af[2][4];
            #pragma unroll
            for (int mi = 0; mi < 2; mi++){
                int r = wm + mi * 16 + (lane >> 2);
                int c = kb + (lane & 3);
                af[mi][0] = As[cur][r * ASS + c];
                af[mi][1] = As[cur][(r + 8) * ASS + c];
                af[mi][2] = As[cur][r * ASS + c + 4];
                af[mi][3] = As[cur][(r + 8) * ASS + c + 4];
            }
            #pragma unroll
            for (int ni = 0; ni < 8; ni++){
                int n = wn + ni * 8 + (lane >> 2);
                uint32_t bf[2];
                bf[0] = Bs[cur][(kb + (lane & 3)) * BSS + n];
                bf[1] = Bs[cur][(kb + (lane & 3) + 4) * BSS + n];
                #pragma unroll
                for (int mi = 0; mi < 2; mi++) mma_tf32(acc[mi][ni], af[mi], bf);
            }
        }
        if (kt + 1 < KT){
            STS(cur ^ 1, kt + 1);
            __syncthreads();
        }
    }

    if (MODE == 0){
        float* C = (yy < 2) ? g_mu : g_lv;
        #pragma unroll
        for (int mi = 0; mi < 2; mi++){
            int r0 = m0 + wm + mi * 16 + (lane >> 2);
            #pragma unroll
            for (int ni = 0; ni < 8; ni++){
                int c = n0 + wn + ni * 8 + 2 * (lane & 3);
                float b0 = biasv[c], b1 = biasv[c + 1];
                float4 a = acc[mi][ni];
                *(float2*)(C + (size_t)r0 * L_ + c)       = make_float2(a.x + b0, a.y + b1);
                *(float2*)(C + (size_t)(r0 + 8) * L_ + c) = make_float2(a.z + b0, a.w + b1);
            }
        }
    } else {
        __shared__ float brow[BMg];
        for (int i = tid; i < BMg; i += 256) brow[i] = 0.f;
        __syncthreads();
        #pragma unroll
        for (int mi = 0; mi < 2; mi++){
            float s0 = 0.f, s1 = 0.f;
            #pragma unroll
            for (int ni = 0; ni < 8; ni++){
                int c = n0 + wn + ni * 8 + 2 * (lane & 3);
                float w0 = bm2w[c], w1 = bm2w[c + 1];
                float b0 = biasv[c], b1 = biasv[c + 1];
                float4 a = acc[mi][ni];
                s0 += fmaxf(a.x + b0, 0.f) * w0 + fmaxf(a.y + b1, 0.f) * w1;
                s1 += fmaxf(a.z + b0, 0.f) * w0 + fmaxf(a.w + b1, 0.f) * w1;
            }
            s0 += __shfl_xor_sync(0xffffffffu, s0, 1);
            s0 += __shfl_xor_sync(0xffffffffu, s0, 2);
            s1 += __shfl_xor_sync(0xffffffffu, s1, 1);
            s1 += __shfl_xor_sync(0xffffffffu, s1, 2);
            if ((lane & 3) == 0){
                atomicAdd(&brow[wm + mi * 16 + (lane >> 2)], s0);
                atomicAdd(&brow[wm + mi * 16 + (lane >> 2) + 8], s1);
            }
        }
        __syncthreads();
        for (int i = tid; i < BMg; i += 256)
            atomicAdd(&g_bias[m0 + i], brow[i]);
    }
}

// ---------------- K34: fused z/LN/kl/dot + softmax + context (block per batch) ----
__global__ void k34_fused(const float* __restrict__ eps,
                          const float* __restrict__ post_w, const float* __restrict__ post_b,
                          const float* __restrict__ trust, const float* __restrict__ comm,
                          const float* __restrict__ bm2_b){
    extern __shared__ float zsh[];   // [64][L_] = 64 KB
    __shared__ float s_dot[N_], s_kl[N_], s_w[N_];
    int b = blockIdx.x, tid = threadIdx.x;
    int wi = tid >> 5, lane = tid & 31;

    float4 pw0 = *(const float4*)(post_w + lane * 4);
    float4 pw1 = *(const float4*)(post_w + 128 + lane * 4);
    float4 pb0 = *(const float4*)(post_b + lane * 4);
    float4 pb1 = *(const float4*)(post_b + 128 + lane * 4);
    float4 qv0 = *(const float4*)(g_qk + (size_t)b * L_ + lane * 4);
    float4 qv1 = *(const float4*)(g_qk + (size_t)b * L_ + 128 + lane * 4);

    #pragma unroll
    for (int j = 0; j < 8; j++){
        int n = wi * 8 + j;
        size_t base = ((size_t)(b * N_ + n)) * L_;
        float4 m0 = *(const float4*)(g_mu + base + lane * 4);
        float4 m1 = *(const float4*)(g_mu + base + 128 + lane * 4);
        float4 l0 = *(const float4*)(g_lv + base + lane * 4);
        float4 l1 = *(const float4*)(g_lv + base + 128 + lane * 4);
        float4 e0 = *(const float4*)(eps + base + lane * 4);
        float4 e1 = *(const float4*)(eps + base + 128 + lane * 4);
        float zp[8];
        zp[0] = m0.x + e0.x * expf(0.5f * l0.x);
        zp[1] = m0.y + e0.y * expf(0.5f * l0.y);
        zp[2] = m0.z + e0.z * expf(0.5f * l0.z);
        zp[3] = m0.w + e0.w * expf(0.5f * l0.w);
        zp[4] = m1.x + e1.x * expf(0.5f * l1.x);
        zp[5] = m1.y + e1.y * expf(0.5f * l1.y);
        zp[6] = m1.z + e1.z * expf(0.5f * l1.z);
        zp[7] = m1.w + e1.w * expf(0.5f * l1.w);
        float s = 0.f;
        #pragma unroll
        for (int i = 0; i < 8; i++) s += zp[i];
        float mean = warpSum(s) * (1.f / 256.f);
        float v = 0.f;
        #pragma unroll
        for (int i = 0; i < 8; i++){ float d = zp[i] - mean; v += d * d; }
        float rstd = rsqrtf(warpSum(v) * (1.f / 256.f) + 1e-5f);
        float4 z0, z1;
        z0.x = (zp[0] - mean) * rstd * pw0.x + pb0.x;
        z0.y = (zp[1] - mean) * rstd * pw0.y + pb0.y;
        z0.z = (zp[2] - mean) * rstd * pw0.z + pb0.z;
        z0.w = (zp[3] - mean) * rstd * pw0.w + pb0.w;
        z1.x = (zp[4] - mean) * rstd * pw1.x + pb1.x;
        z1.y = (zp[5] - mean) * rstd * pw1.y + pb1.y;
        z1.z = (zp[6] - mean) * rstd * pw1.z + pb1.z;
        z1.w = (zp[7] - mean) * rstd * pw1.w + pb1.w;
        *(float4*)(zsh + n * L_ + lane * 4)       = z0;
        *(float4*)(zsh + n * L_ + 128 + lane * 4) = z1;
        float dp = z0.x*qv0.x + z0.y*qv0.y + z0.z*qv0.z + z0.w*qv0.w
                 + z1.x*qv1.x + z1.y*qv1.y + z1.z*qv1.z + z1.w*qv1.w;
        dp = warpSum(dp);
        float kl = (1.f + l0.x - m0.x*m0.x - expf(l0.x))
                 + (1.f + l0.y - m0.y*m0.y - expf(l0.y))
                 + (1.f + l0.z - m0.z*m0.z - expf(l0.z))
                 + (1.f + l0.w - m0.w*m0.w - expf(l0.w))
                 + (1.f + l1.x - m1.x*m1.x - expf(l1.x))
                 + (1.f + l1.y - m1.y*m1.y - expf(l1.y))
                 + (1.f + l1.z - m1.z*m1.z - expf(l1.z))
                 + (1.f + l1.w - m1.w*m1.w - expf(l1.w));
        kl = warpSum(kl);
        if (lane == 0){ s_dot[n] = dp; s_kl[n] = -0.5f * kl; }
    }
    __syncthreads();

    if (tid == 0){
        float lg[N_], nm[N_];
        float qkb = g_qkb[b], b2 = bm2_b[0];
        float mx = -3.4e38f;
        for (int n = 0; n < N_; n++){
            int row = b * N_ + n;
            float m = comm[row];
            nm[n] = m;
            float l;
            if (m < 0.5f) l = -1e9f;
            else l = (s_dot[n] + qkb) * 0.0625f - (g_bias[row] + b2)
                     + logf(trust[row] + 1e-6f);
            lg[n] = l;
            mx = fmaxf(mx, l);
        }
        float se = 0.f;
        for (int n = 0; n < N_; n++) se += expf(lg[n] - mx);
        float wsum = 0.f;
        for (int n = 0; n < N_; n++){
            float w = expf(lg[n] - mx) / se * nm[n];
            s_w[n] = w; wsum += w;
        }
        float denom = fmaxf(wsum, 1e-6f);
        float tot = 0.f, klp = 0.f, nmp = 0.f;
        for (int n = 0; n < N_; n++){
            s_w[n] /= denom;
            tot += s_w[n];
            klp += s_kl[n] * nm[n];
            nmp += nm[n];
        }
        g_sw[b] = tot;
        atomicAdd(&g_klsum, klp);
        atomicAdd(&g_nmsum, nmp);
    }
    __syncthreads();

    float acc = 0.f;
    #pragma unroll 8
    for (int n = 0; n < N_; n++) acc += s_w[n] * zsh[n * L_ + tid];
    g_ctx[(size_t)b * L_ + tid] = acc;
}

// ---------------- K5: context@v_w -> @out_w -> comm_feat ----------------
__global__ void k5_out(const float* __restrict__ v_w, const float* __restrict__ v_b,
                       const float* __restrict__ out_w, const float* __restrict__ out_b,
                       float* __restrict__ out){
    __shared__ float s_cx[16][L_];
    __shared__ float s_c2[16][L_];
    __shared__ float s_sw[16];
    int b0 = blockIdx.x * 16;
    int tid = threadIdx.x;
    for (int idx = tid; idx < 16 * L_; idx += 256){
        int r = idx >> 8, l = idx & 255;
        s_cx[r][l] = g_ctx[(size_t)(b0 + r) * L_ + l];
    }
    if (tid < 16) s_sw[tid] = g_sw[b0 + tid];
    __syncthreads();
    {
        float acc[16] = {};
        for (int l = 0; l < L_; l++){
            float w = v_w[(size_t)l * L_ + tid];
            #pragma unroll
            for (int r = 0; r < 16; r++) acc[r] += s_cx[r][l] * w;
        }
        float vb = v_b[tid];
        #pragma unroll
        for (int r = 0; r < 16; r++) s_c2[r][tid] = acc[r] + vb * s_sw[r];
    }
    __syncthreads();
    for (int hh = 0; hh < 2; hh++){
        int h = tid + hh * 256;
        float acc[16] = {};
        for (int l = 0; l < L_; l++){
            float w = out_w[(size_t)l * H_ + h];
            #pragma unroll
            for (int r = 0; r < 16; r++) acc[r] += s_c2[r][l] * w;
        }
        float ob = out_b[h];
        #pragma unroll
        for (int r = 0; r < 16; r++) out[(size_t)(b0 + r) * H_ + h] = acc[r] + ob;
    }
}

// ---------------- K6: kl scalars ----------------
__global__ void k6_kl(float* __restrict__ out){
    float klraw = g_klsum / fmaxf(g_nmsum, 1.f);
    out[(size_t)B_ * H_]     = 0.01f * klraw;
    out[(size_t)B_ * H_ + 1] = klraw;
}

// ---------------- launch ----------------
extern "C" void kernel_launch(void* const* d_in, const int* in_sizes, int n_in,
                              void* d_out, int out_size){
    const float* self   = (const float*)d_in[0];
    const float* neigh  = (const float*)d_in[1];
    const float* trust  = (const float*)d_in[2];
    const float* comm   = (const float*)d_in[3];
    const float* eps    = (const float*)d_in[4];
    const float* pre_w  = (const float*)d_in[5];
    const float* pre_b  = (const float*)d_in[6];
    const float* mu_w   = (const float*)d_in[7];
    const float* mu_b   = (const float*)d_in[8];
    const float* lv_w   = (const float*)d_in[9];
    const float* lv_b   = (const float*)d_in[10];
    const float* post_w = (const float*)d_in[11];
    const float* post_b = (const float*)d_in[12];
    const float* q_w    = (const float*)d_in[13];
    const float* q_b    = (const float*)d_in[14];
    const float* k_w    = (const float*)d_in[15];
    const float* k_b    = (const float*)d_in[16];
    const float* v_w    = (const float*)d_in[17];
    const float* v_b    = (const float*)d_in[18];
    const float* out_w  = (const float*)d_in[19];
    const float* out_b  = (const float*)d_in[20];
    const float* bm1_w  = (const float*)d_in[21];
    const float* bm1_b  = (const float*)d_in[22];
    const float* bm2_w  = (const float*)d_in[23];
    const float* bm2_b  = (const float*)d_in[24];
    float* out = (float*)d_out;

    static bool attr_done = false;
    if (!attr_done){
        cudaFuncSetAttribute(k34_fused, cudaFuncAttributeMaxDynamicSharedMemorySize,
                             N_ * L_ * sizeof(float));
        attr_done = true;
    }

    k0_stats<<<M_ / 8, 256>>>(neigh);
    k1_query<<<B_ / 8, 256>>>(self, q_w, q_b, k_w, k_b);
    gemm_tf32<0><<<dim3(M_ / BMg, 4), 256>>>(neigh, nullptr, pre_w, pre_b,
                                             mu_w, mu_b, lv_w, lv_b, nullptr);
    gemm_tf32<1><<<dim3(M_ / BMg, 4), 256>>>(neigh, self, nullptr, nullptr,
                                             bm1_w, bm1_b, nullptr, nullptr, bm2_w);
    k34_fused<<<B_, 256, N_ * L_ * sizeof(float)>>>(eps, post_w, post_b, trust, comm, bm2_b);
    k5_out<<<B_ / 16, 256>>>(v_w, v_b, out_w, out_b, out);
    k6_kl<<<1, 1>>>(out);
}

// round 6
// speedup vs baseline: 2.7519x; 1.0138x over previous
#include <cuda_runtime.h>
#include <math.h>
#include <stdint.h>

#define B_  2048
#define N_  64
#define H_  512
#define L_  256
#define M_  (B_*N_)    // 131072 edges

// ---------------- scratch ----------------
__device__ float g_mu [ (size_t)M_ * L_ ];
__device__ float g_lv [ (size_t)M_ * L_ ];
__device__ float g_mean[M_];
__device__ float g_rstd[M_];
__device__ float g_bias[M_];
__device__ float g_qk  [B_ * L_];
__device__ float g_qkb [B_];
__device__ float g_ctx [B_ * L_];
__device__ float g_sw  [B_];
__device__ float g_klsum;
__device__ float g_nmsum;
// pre-converted tf32 weights
__device__ uint32_t g_muw_t [H_ * L_];
__device__ uint32_t g_lvw_t [H_ * L_];
__device__ uint32_t g_bm1w_t[H_ * H_];

// ---------------- helpers ----------------
__device__ __forceinline__ uint32_t f2tf(float x){
    uint32_t u; asm("cvt.rna.tf32.f32 %0, %1;" : "=r"(u) : "f"(x)); return u;
}
__device__ __forceinline__ void mma_tf32(float4& d, const uint32_t a[4], const uint32_t b[2]){
    asm volatile("mma.sync.aligned.m16n8k8.row.col.f32.tf32.tf32.f32 "
        "{%0,%1,%2,%3}, {%4,%5,%6,%7}, {%8,%9}, {%0,%1,%2,%3};\n"
        : "+f"(d.x), "+f"(d.y), "+f"(d.z), "+f"(d.w)
        : "r"(a[0]), "r"(a[1]), "r"(a[2]), "r"(a[3]), "r"(b[0]), "r"(b[1]));
}
__device__ __forceinline__ float warpSum(float v){
    #pragma unroll
    for (int o = 16; o; o >>= 1) v += __shfl_xor_sync(0xffffffffu, v, o);
    return v;
}
__device__ __forceinline__ void cp16(uint32_t dst, const void* src){
    asm volatile("cp.async.cg.shared.global [%0], [%1], 16;" :: "r"(dst), "l"(src));
}
#define CP_COMMIT() asm volatile("cp.async.commit_group;")
#define CP_WAIT0()  asm volatile("cp.async.wait_group 0;")

// ---------------- KW: convert weights to tf32 (once per call, ~10us) -----------
__global__ void kw_conv(const float* __restrict__ mu_w, const float* __restrict__ lv_w,
                        const float* __restrict__ bm1_w){
    int i = blockIdx.x * 256 + threadIdx.x;      // grid covers H_*H_ = 262144
    if (i < H_ * L_){
        g_muw_t[i] = f2tf(mu_w[i]);
        g_lvw_t[i] = f2tf(lv_w[i]);
    }
    g_bm1w_t[i] = f2tf(bm1_w[i]);
}

// ---------------- K0: per-row LN stats (warp per row) + zero accumulators --------
__global__ void k0_stats(const float* __restrict__ neigh){
    int row = blockIdx.x * 8 + (threadIdx.x >> 5);
    int lane = threadIdx.x & 31;
    const float4* x = (const float4*)(neigh + (size_t)row * H_);
    float s = 0.f, ss = 0.f;
    #pragma unroll
    for (int i = 0; i < 4; i++){
        float4 v = x[lane + 32 * i];
        s  += v.x + v.y + v.z + v.w;
        ss += v.x*v.x + v.y*v.y + v.z*v.z + v.w*v.w;
    }
    s = warpSum(s); ss = warpSum(ss);
    if (lane == 0){
        float mean = s * (1.f / 512.f);
        float var  = ss * (1.f / 512.f) - mean * mean;
        g_mean[row] = mean;
        g_rstd[row] = rsqrtf(var + 1e-5f);
        g_bias[row] = 0.f;
        if (row == 0){ g_klsum = 0.f; g_nmsum = 0.f; }
    }
}

// ---------------- K1: query = self@q_w + q_b ; qk = query@k_w^T ; qkb = query.k_b --
__global__ void k1_query(const float* __restrict__ self,
                         const float* __restrict__ q_w, const float* __restrict__ q_b,
                         const float* __restrict__ k_w, const float* __restrict__ k_b){
    __shared__ float s_self[8][H_];
    __shared__ float s_q[8][L_];
    int b0 = blockIdx.x * 8;
    int tid = threadIdx.x;
    for (int idx = tid; idx < 8 * H_; idx += 256){
        int r = idx >> 9, h = idx & 511;
        s_self[r][h] = self[(size_t)(b0 + r) * H_ + h];
    }
    __syncthreads();
    {
        float acc[8] = {};
        for (int h = 0; h < H_; h++){
            float w = q_w[(size_t)h * L_ + tid];
            #pragma unroll
            for (int r = 0; r < 8; r++) acc[r] += s_self[r][h] * w;
        }
        float qb = q_b[tid];
        #pragma unroll
        for (int r = 0; r < 8; r++) s_q[r][tid] = acc[r] + qb;
    }
    __syncthreads();
    {
        float acc[8] = {};
        for (int l = 0; l < L_; l++){
            float w = k_w[(size_t)tid * L_ + l];
            #pragma unroll
            for (int r = 0; r < 8; r++) acc[r] += s_q[r][l] * w;
        }
        #pragma unroll
        for (int r = 0; r < 8; r++) g_qk[(size_t)(b0 + r) * L_ + tid] = acc[r];
    }
    int w = tid >> 5, lane = tid & 31;
    float p = 0.f;
    for (int l = lane; l < L_; l += 32) p += s_q[w][l] * k_b[l];
    p = warpSum(p);
    if (lane == 0) g_qkb[b0 + w] = p;
}

// ---------------- K2: fused tf32 GEMM, one launch, all three products ------------
// grid = (8, M_/128). blockIdx.x = n-slice (A-tile shared in L2 by 8 blocks):
//   yy 0,1: mu   cols [0,128),[128,256)   A = LN(neigh)
//   yy 2,3: lv   cols [0,128),[128,256)   A = LN(neigh)
//   yy 4..7: bias-MLP cols yy*128         A = |self-neigh|, relu.bm2 reduce
#define BMg 128
#define BNg 128
#define BKg 16
#define ASS (BKg + 4)    // 20: conflict-free A frag loads
#define BSS (BNg + 8)    // 136: conflict-free B frag loads

__global__ __launch_bounds__(256)
void gemm_fused(const float* __restrict__ neigh, const float* __restrict__ self,
                const float* __restrict__ pre_w, const float* __restrict__ pre_b,
                const float* __restrict__ mu_b, const float* __restrict__ lv_b,
                const float* __restrict__ bm1_b, const float* __restrict__ bm2w){
    __shared__ __align__(16) uint32_t As[2][BMg * ASS];
    __shared__ __align__(16) uint32_t Bs[2][BKg * BSS];
    __shared__ float s_mean[BMg], s_rstd[BMg];
    __shared__ float s_prew[H_], s_preb[H_];

    int yy = blockIdx.x;
    int m0 = blockIdx.y * BMg;
    int tid = threadIdx.x;
    int lane = tid & 31, w = tid >> 5;
    bool isBias = (yy >= 4);

    const uint32_t* Bw; const float* biasv; float* C = nullptr; int n0, Ncols;
    if (yy < 2){ Bw = g_muw_t; biasv = mu_b; C = g_mu; n0 = yy * 128; Ncols = L_; }
    else if (yy < 4){ Bw = g_lvw_t; biasv = lv_b; C = g_lv; n0 = (yy - 2) * 128; Ncols = L_; }
    else { Bw = g_bm1w_t; biasv = bm1_b; n0 = (yy - 4) * 128; Ncols = H_; }

    if (!isBias){
        for (int i = tid; i < BMg; i += 256){
            s_mean[i] = g_mean[m0 + i]; s_rstd[i] = g_rstd[m0 + i];
        }
        for (int i = tid; i < H_; i += 256){
            s_prew[i] = pre_w[i]; s_preb[i] = pre_b[i];
        }
        __syncthreads();
    }

    int am = tid >> 2;            // 0..63
    int ak = (tid & 3) * 4;       // 0,4,8,12
    int bn4 = lane * 4;
    int wm = (w & 3) * 32;
    int wn = (w >> 2) * 64;

    uint32_t bs0 = (uint32_t)__cvta_generic_to_shared(&Bs[0][0]);
    uint32_t bs1 = (uint32_t)__cvta_generic_to_shared(&Bs[1][0]);

    float4 acc[2][8];
    #pragma unroll
    for (int i = 0; i < 2; i++)
        #pragma unroll
        for (int j = 0; j < 8; j++) acc[i][j] = make_float4(0.f, 0.f, 0.f, 0.f);

    const int KT = H_ / BKg;     // 32
    float4 vA0, vA1, vS0, vS1;

    auto LDG_A = [&](int kt){
        int k0 = kt * BKg;
        vA0 = *(const float4*)(neigh + (size_t)(m0 + am) * H_ + k0 + ak);
        vA1 = *(const float4*)(neigh + (size_t)(m0 + am + 64) * H_ + k0 + ak);
        if (isBias){
            vS0 = *(const float4*)(self + (size_t)((m0 + am) >> 6) * H_ + k0 + ak);
            vS1 = *(const float4*)(self + (size_t)((m0 + am + 64) >> 6) * H_ + k0 + ak);
        }
    };
    auto CPA_B = [&](int kt, int buf){
        int k0 = kt * BKg;
        uint32_t base = buf ? bs1 : bs0;
        cp16(base + (w * BSS + bn4) * 4,       Bw + (size_t)(k0 + w) * Ncols + n0 + bn4);
        cp16(base + ((w + 8) * BSS + bn4) * 4, Bw + (size_t)(k0 + w + 8) * Ncols + n0 + bn4);
    };
    auto STS_A = [&](int buf, int kt){
        int k0 = kt * BKg;
        float x0, x1, x2, x3;
        if (!isBias){
            float mn = s_mean[am], rs = s_rstd[am];
            x0 = (vA0.x - mn) * rs * s_prew[k0+ak+0] + s_preb[k0+ak+0];
            x1 = (vA0.y - mn) * rs * s_prew[k0+ak+1] + s_preb[k0+ak+1];
            x2 = (vA0.z - mn) * rs * s_prew[k0+ak+2] + s_preb[k0+ak+2];
            x3 = (vA0.w - mn) * rs * s_prew[k0+ak+3] + s_preb[k0+ak+3];
        } else {
            x0 = fabsf(vS0.x - vA0.x); x1 = fabsf(vS0.y - vA0.y);
            x2 = fabsf(vS0.z - vA0.z); x3 = fabsf(vS0.w - vA0.w);
        }
        *(uint4*)&As[buf][am * ASS + ak] = make_uint4(f2tf(x0), f2tf(x1), f2tf(x2), f2tf(x3));
        if (!isBias){
            float mn = s_mean[am + 64], rs = s_rstd[am + 64];
            x0 = (vA1.x - mn) * rs * s_prew[k0+ak+0] + s_preb[k0+ak+0];
            x1 = (vA1.y - mn) * rs * s_prew[k0+ak+1] + s_preb[k0+ak+1];
            x2 = (vA1.z - mn) * rs * s_prew[k0+ak+2] + s_preb[k0+ak+2];
            x3 = (vA1.w - mn) * rs * s_prew[k0+ak+3] + s_preb[k0+ak+3];
        } else {
            x0 = fabsf(vS1.x - vA1.x); x1 = fabsf(vS1.y - vA1.y);
            x2 = fabsf(vS1.z - vA1.z); x3 = fabsf(vS1.w - vA1.w);
        }
        *(uint4*)&As[buf][(am + 64) * ASS + ak] = make_uint4(f2tf(x0), f2tf(x1), f2tf(x2), f2tf(x3));
    };

    CPA_B(0, 0); CP_COMMIT();
    LDG_A(0); STS_A(0, 0);
    CP_WAIT0();
    __syncthreads();

    for (int kt = 0; kt < KT; kt++){
        int cur = kt & 1;
        if (kt + 1 < KT){
            CPA_B(kt + 1, cur ^ 1); CP_COMMIT();
            LDG_A(kt + 1);
        }
        #pragma unroll
        for (int ks = 0; ks < 2; ks++){
            int kb = ks * 8;
            uint32_t af[2][4];
            #pragma unroll
            for (int mi = 0; mi < 2; mi++){
                int r = wm + mi * 16 + (lane >> 2);
                int c = kb + (lane & 3);
                af[mi][0] = As[cur][r * ASS + c];
                af[mi][1] = As[cur][(r + 8) * ASS + c];
                af[mi][2] = As[cur][r * ASS + c + 4];
                af[mi][3] = As[cur][(r + 8) * ASS + c + 4];
            }
            #pragma unroll
            for (int ni = 0; ni < 8; ni++){
                int n = wn + ni * 8 + (lane >> 2);
                uint32_t bf[2];
                bf[0] = Bs[cur][(kb + (lane & 3)) * BSS + n];
                bf[1] = Bs[cur][(kb + (lane & 3) + 4) * BSS + n];
                #pragma unroll
                for (int mi = 0; mi < 2; mi++) mma_tf32(acc[mi][ni], af[mi], bf);
            }
        }
        if (kt + 1 < KT){
            STS_A(cur ^ 1, kt + 1);
            CP_WAIT0();
            __syncthreads();
        }
    }

    if (!isBias){
        #pragma unroll
        for (int mi = 0; mi < 2; mi++){
            int r0 = m0 + wm + mi * 16 + (lane >> 2);
            #pragma unroll
            for (int ni = 0; ni < 8; ni++){
                int c = n0 + wn + ni * 8 + 2 * (lane & 3);
                float b0 = biasv[c], b1 = biasv[c + 1];
                float4 a = acc[mi][ni];
                *(float2*)(C + (size_t)r0 * L_ + c)       = make_float2(a.x + b0, a.y + b1);
                *(float2*)(C + (size_t)(r0 + 8) * L_ + c) = make_float2(a.z + b0, a.w + b1);
            }
        }
    } else {
        __shared__ float brow[BMg];
        for (int i = tid; i < BMg; i += 256) brow[i] = 0.f;
        __syncthreads();
        #pragma unroll
        for (int mi = 0; mi < 2; mi++){
            float s0 = 0.f, s1 = 0.f;
            #pragma unroll
            for (int ni = 0; ni < 8; ni++){
                int c = n0 + wn + ni * 8 + 2 * (lane & 3);
                float w0 = bm2w[c], w1 = bm2w[c + 1];
                float b0 = biasv[c], b1 = biasv[c + 1];
                float4 a = acc[mi][ni];
                s0 += fmaxf(a.x + b0, 0.f) * w0 + fmaxf(a.y + b1, 0.f) * w1;
                s1 += fmaxf(a.z + b0, 0.f) * w0 + fmaxf(a.w + b1, 0.f) * w1;
            }
            s0 += __shfl_xor_sync(0xffffffffu, s0, 1);
            s0 += __shfl_xor_sync(0xffffffffu, s0, 2);
            s1 += __shfl_xor_sync(0xffffffffu, s1, 1);
            s1 += __shfl_xor_sync(0xffffffffu, s1, 2);
            if ((lane & 3) == 0){
                atomicAdd(&brow[wm + mi * 16 + (lane >> 2)], s0);
                atomicAdd(&brow[wm + mi * 16 + (lane >> 2) + 8], s1);
            }
        }
        __syncthreads();
        for (int i = tid; i < BMg; i += 256)
            atomicAdd(&g_bias[m0 + i], brow[i]);
    }
}

// ---------------- K34: fused z/LN/kl/dot + softmax + context (block per batch) ----
__global__ void k34_fused(const float* __restrict__ eps,
                          const float* __restrict__ post_w, const float* __restrict__ post_b,
                          const float* __restrict__ trust, const float* __restrict__ comm,
                          const float* __restrict__ bm2_b){
    extern __shared__ float zsh[];   // [64][L_] = 64 KB
    __shared__ float s_dot[N_], s_kl[N_], s_w[N_];
    int b = blockIdx.x, tid = threadIdx.x;
    int wi = tid >> 5, lane = tid & 31;

    float4 pw0 = *(const float4*)(post_w + lane * 4);
    float4 pw1 = *(const float4*)(post_w + 128 + lane * 4);
    float4 pb0 = *(const float4*)(post_b + lane * 4);
    float4 pb1 = *(const float4*)(post_b + 128 + lane * 4);
    float4 qv0 = *(const float4*)(g_qk + (size_t)b * L_ + lane * 4);
    float4 qv1 = *(const float4*)(g_qk + (size_t)b * L_ + 128 + lane * 4);

    #pragma unroll
    for (int j = 0; j < 8; j++){
        int n = wi * 8 + j;
        size_t base = ((size_t)(b * N_ + n)) * L_;
        float4 m0 = *(const float4*)(g_mu + base + lane * 4);
        float4 m1 = *(const float4*)(g_mu + base + 128 + lane * 4);
        float4 l0 = *(const float4*)(g_lv + base + lane * 4);
        float4 l1 = *(const float4*)(g_lv + base + 128 + lane * 4);
        float4 e0 = *(const float4*)(eps + base + lane * 4);
        float4 e1 = *(const float4*)(eps + base + 128 + lane * 4);
        float zp[8];
        zp[0] = m0.x + e0.x * expf(0.5f * l0.x);
        zp[1] = m0.y + e0.y * expf(0.5f * l0.y);
        zp[2] = m0.z + e0.z * expf(0.5f * l0.z);
        zp[3] = m0.w + e0.w * expf(0.5f * l0.w);
        zp[4] = m1.x + e1.x * expf(0.5f * l1.x);
        zp[5] = m1.y + e1.y * expf(0.5f * l1.y);
        zp[6] = m1.z + e1.z * expf(0.5f * l1.z);
        zp[7] = m1.w + e1.w * expf(0.5f * l1.w);
        float s = 0.f;
        #pragma unroll
        for (int i = 0; i < 8; i++) s += zp[i];
        float mean = warpSum(s) * (1.f / 256.f);
        float v = 0.f;
        #pragma unroll
        for (int i = 0; i < 8; i++){ float d = zp[i] - mean; v += d * d; }
        float rstd = rsqrtf(warpSum(v) * (1.f / 256.f) + 1e-5f);
        float4 z0, z1;
        z0.x = (zp[0] - mean) * rstd * pw0.x + pb0.x;
        z0.y = (zp[1] - mean) * rstd * pw0.y + pb0.y;
        z0.z = (zp[2] - mean) * rstd * pw0.z + pb0.z;
        z0.w = (zp[3] - mean) * rstd * pw0.w + pb0.w;
        z1.x = (zp[4] - mean) * rstd * pw1.x + pb1.x;
        z1.y = (zp[5] - mean) * rstd * pw1.y + pb1.y;
        z1.z = (zp[6] - mean) * rstd * pw1.z + pb1.z;
        z1.w = (zp[7] - mean) * rstd * pw1.w + pb1.w;
        *(float4*)(zsh + n * L_ + lane * 4)       = z0;
        *(float4*)(zsh + n * L_ + 128 + lane * 4) = z1;
        float dp = z0.x*qv0.x + z0.y*qv0.y + z0.z*qv0.z + z0.w*qv0.w
                 + z1.x*qv1.x + z1.y*qv1.y + z1.z*qv1.z + z1.w*qv1.w;
        dp = warpSum(dp);
        float kl = (1.f + l0.x - m0.x*m0.x - expf(l0.x))
                 + (1.f + l0.y - m0.y*m0.y - expf(l0.y))
                 + (1.f + l0.z - m0.z*m0.z - expf(l0.z))
                 + (1.f + l0.w - m0.w*m0.w - expf(l0.w))
                 + (1.f + l1.x - m1.x*m1.x - expf(l1.x))
                 + (1.f + l1.y - m1.y*m1.y - expf(l1.y))
                 + (1.f + l1.z - m1.z*m1.z - expf(l1.z))
                 + (1.f + l1.w - m1.w*m1.w - expf(l1.w));
        kl = warpSum(kl);
        if (lane == 0){ s_dot[n] = dp; s_kl[n] = -0.5f * kl; }
    }
    __syncthreads();

    if (tid == 0){
        float lg[N_], nm[N_];
        float qkb = g_qkb[b], b2 = bm2_b[0];
        float mx = -3.4e38f;
        for (int n = 0; n < N_; n++){
            int row = b * N_ + n;
            float m = comm[row];
            nm[n] = m;
            float l;
            if (m < 0.5f) l = -1e9f;
            else l = (s_dot[n] + qkb) * 0.0625f - (g_bias[row] + b2)
                     + logf(trust[row] + 1e-6f);
            lg[n] = l;
            mx = fmaxf(mx, l);
        }
        float se = 0.f;
        for (int n = 0; n < N_; n++) se += expf(lg[n] - mx);
        float wsum = 0.f;
        for (int n = 0; n < N_; n++){
            float w = expf(lg[n] - mx) / se * nm[n];
            s_w[n] = w; wsum += w;
        }
        float denom = fmaxf(wsum, 1e-6f);
        float tot = 0.f, klp = 0.f, nmp = 0.f;
        for (int n = 0; n < N_; n++){
            s_w[n] /= denom;
            tot += s_w[n];
            klp += s_kl[n] * nm[n];
            nmp += nm[n];
        }
        g_sw[b] = tot;
        atomicAdd(&g_klsum, klp);
        atomicAdd(&g_nmsum, nmp);
    }
    __syncthreads();

    float acc = 0.f;
    #pragma unroll 8
    for (int n = 0; n < N_; n++) acc += s_w[n] * zsh[n * L_ + tid];
    g_ctx[(size_t)b * L_ + tid] = acc;
}

// ---------------- K5: context@v_w -> @out_w -> comm_feat ----------------
__global__ void k5_out(const float* __restrict__ v_w, const float* __restrict__ v_b,
                       const float* __restrict__ out_w, const float* __restrict__ out_b,
                       float* __restrict__ out){
    __shared__ float s_cx[16][L_];
    __shared__ float s_c2[16][L_];
    __shared__ float s_sw[16];
    int b0 = blockIdx.x * 16;
    int tid = threadIdx.x;
    for (int idx = tid; idx < 16 * L_; idx += 256){
        int r = idx >> 8, l = idx & 255;
        s_cx[r][l] = g_ctx[(size_t)(b0 + r) * L_ + l];
    }
    if (tid < 16) s_sw[tid] = g_sw[b0 + tid];
    __syncthreads();
    {
        float acc[16] = {};
        for (int l = 0; l < L_; l++){
            float w = v_w[(size_t)l * L_ + tid];
            #pragma unroll
            for (int r = 0; r < 16; r++) acc[r] += s_cx[r][l] * w;
        }
        float vb = v_b[tid];
        #pragma unroll
        for (int r = 0; r < 16; r++) s_c2[r][tid] = acc[r] + vb * s_sw[r];
    }
    __syncthreads();
    for (int hh = 0; hh < 2; hh++){
        int h = tid + hh * 256;
        float acc[16] = {};
        for (int l = 0; l < L_; l++){
            float w = out_w[(size_t)l * H_ + h];
            #pragma unroll
            for (int r = 0; r < 16; r++) acc[r] += s_c2[r][l] * w;
        }
        float ob = out_b[h];
        #pragma unroll
        for (int r = 0; r < 16; r++) out[(size_t)(b0 + r) * H_ + h] = acc[r] + ob;
    }
}

// ---------------- K6: kl scalars ----------------
__global__ void k6_kl(float* __restrict__ out){
    float klraw = g_klsum / fmaxf(g_nmsum, 1.f);
    out[(size_t)B_ * H_]     = 0.01f * klraw;
    out[(size_t)B_ * H_ + 1] = klraw;
}

// ---------------- launch ----------------
extern "C" void kernel_launch(void* const* d_in, const int* in_sizes, int n_in,
                              void* d_out, int out_size){
    const float* self   = (const float*)d_in[0];
    const float* neigh  = (const float*)d_in[1];
    const float* trust  = (const float*)d_in[2];
    const float* comm   = (const float*)d_in[3];
    const float* eps    = (const float*)d_in[4];
    const float* pre_w  = (const float*)d_in[5];
    const float* pre_b  = (const float*)d_in[6];
    const float* mu_w   = (const float*)d_in[7];
    const float* mu_b   = (const float*)d_in[8];
    const float* lv_w   = (const float*)d_in[9];
    const float* lv_b   = (const float*)d_in[10];
    const float* post_w = (const float*)d_in[11];
    const float* post_b = (const float*)d_in[12];
    const float* q_w    = (const float*)d_in[13];
    const float* q_b    = (const float*)d_in[14];
    const float* k_w    = (const float*)d_in[15];
    const float* k_b    = (const float*)d_in[16];
    const float* v_w    = (const float*)d_in[17];
    const float* v_b    = (const float*)d_in[18];
    const float* out_w  = (const float*)d_in[19];
    const float* out_b  = (const float*)d_in[20];
    const float* bm1_w  = (const float*)d_in[21];
    const float* bm1_b  = (const float*)d_in[22];
    const float* bm2_w  = (const float*)d_in[23];
    const float* bm2_b  = (const float*)d_in[24];
    float* out = (float*)d_out;

    static bool attr_done = false;
    if (!attr_done){
        cudaFuncSetAttribute(k34_fused, cudaFuncAttributeMaxDynamicSharedMemorySize,
                             N_ * L_ * sizeof(float));
        attr_done = true;
    }

    kw_conv<<<H_ * H_ / 256, 256>>>(mu_w, lv_w, bm1_w);
    k0_stats<<<M_ / 8, 256>>>(neigh);
    k1_query<<<B_ / 8, 256>>>(self, q_w, q_b, k_w, k_b);
    gemm_fused<<<dim3(8, M_ / BMg), 256>>>(neigh, self, pre_w, pre_b,
                                           mu_b, lv_b, bm1_b, bm2_w);
    k34_fused<<<B_, 256, N_ * L_ * sizeof(float)>>>(eps, post_w, post_b, trust, comm, bm2_b);
    k5_out<<<B_ / 16, 256>>>(v_w, v_b, out_w, out_b, out);
    k6_kl<<<1, 1>>>(out);
}